// round 2
// baseline (speedup 1.0000x reference)
#include <cuda_runtime.h>
#include <cuda_bf16.h>
#include <math.h>

// SimpleGNN:
//   deg[s]  = #edges with src==s (clamped >=1 later)
//   agg[s] += x[dst] over edges, then /deg
//   h1 = relu((x+agg) @ W1 + b1)   [N,64]
//   h2 = relu(h1 @ W2 + b2)        [N,64]
//   out = tanh(mean_rows(h2) @ Wh + bh)   (scalar)
//
// Inputs (metadata order): x[N*16] f32, edge_index (int64 in reference, but
// the harness delivers integer tensors as int32 -> const int*), W1[16*64],
// b1[64], W2[64*64], b2[64], Wh[64], bh[1]  (all f32). Output: 1 x f32.

#define MAX_NODES 100000
#define HID 64
#define IN_DIM 16

__device__ float g_agg[MAX_NODES * IN_DIM];
__device__ float g_deg[MAX_NODES];
__device__ float g_hsum[HID];

// ---------------------------------------------------------------------------
// Zero scratch (agg, deg, hsum) — must run every launch (graph replays).
// ---------------------------------------------------------------------------
__global__ void zero_kernel(int n) {
    int total = n * IN_DIM + n + HID;
    for (int i = blockIdx.x * blockDim.x + threadIdx.x; i < total;
         i += gridDim.x * blockDim.x) {
        if (i < n * IN_DIM)           g_agg[i] = 0.0f;
        else if (i < n * IN_DIM + n)  g_deg[i - n * IN_DIM] = 0.0f;
        else                          g_hsum[i - n * IN_DIM - n] = 0.0f;
    }
}

// ---------------------------------------------------------------------------
// Edge scatter: one thread per edge.
//   read src,dst (int32); gather x[dst] as 4x float4; red.v4 into agg[src];
//   deg[src] += 1
// ---------------------------------------------------------------------------
__global__ void edge_kernel(const int* __restrict__ ei,
                            const float* __restrict__ x, int E, int n) {
    int e = blockIdx.x * blockDim.x + threadIdx.x;
    if (e >= E) return;
    int s = ei[e];
    int d = ei[e + E];
    // Defensive: if dtype assumption is wrong this avoids a crash and instead
    // produces a large rel_err (diagnostic). Never triggers when correct.
    if ((unsigned)s >= (unsigned)n || (unsigned)d >= (unsigned)n) return;

    const float4* xr = (const float4*)(x + (size_t)d * IN_DIM);
    float4 v0 = xr[0], v1 = xr[1], v2 = xr[2], v3 = xr[3];

    float* ap = g_agg + (size_t)s * IN_DIM;
    asm volatile("red.global.add.v4.f32 [%0], {%1,%2,%3,%4};"
                 :: "l"(ap), "f"(v0.x), "f"(v0.y), "f"(v0.z), "f"(v0.w) : "memory");
    asm volatile("red.global.add.v4.f32 [%0], {%1,%2,%3,%4};"
                 :: "l"(ap + 4), "f"(v1.x), "f"(v1.y), "f"(v1.z), "f"(v1.w) : "memory");
    asm volatile("red.global.add.v4.f32 [%0], {%1,%2,%3,%4};"
                 :: "l"(ap + 8), "f"(v2.x), "f"(v2.y), "f"(v2.z), "f"(v2.w) : "memory");
    asm volatile("red.global.add.v4.f32 [%0], {%1,%2,%3,%4};"
                 :: "l"(ap + 12), "f"(v3.x), "f"(v3.y), "f"(v3.z), "f"(v3.w) : "memory");
    asm volatile("red.global.add.f32 [%0], %1;"
                 :: "l"(g_deg + s), "f"(1.0f) : "memory");
}

// ---------------------------------------------------------------------------
// Node MLP + partial mean: one thread per node, weights in shared.
// ---------------------------------------------------------------------------
__global__ void __launch_bounds__(256) node_kernel(
    const float* __restrict__ x,
    const float* __restrict__ W1, const float* __restrict__ b1,
    const float* __restrict__ W2, const float* __restrict__ b2,
    int n) {
    __shared__ float sW1[IN_DIM * HID];   // [16][64]
    __shared__ float sb1[HID];
    __shared__ float sW2[HID * HID];      // [64][64]
    __shared__ float sb2[HID];
    __shared__ float ssum[HID];

    int tid = threadIdx.x;
    for (int i = tid; i < IN_DIM * HID; i += blockDim.x) sW1[i] = W1[i];
    for (int i = tid; i < HID * HID;   i += blockDim.x) sW2[i] = W2[i];
    if (tid < HID) { sb1[tid] = b1[tid]; sb2[tid] = b2[tid]; ssum[tid] = 0.0f; }
    __syncthreads();

    int node = blockIdx.x * blockDim.x + tid;
    float h1[HID];
    if (node < n) {
        float deg = fmaxf(g_deg[node], 1.0f);
        float inv = 1.0f / deg;
        float v[IN_DIM];
        const float* xp = x + (size_t)node * IN_DIM;
        const float* ag = g_agg + (size_t)node * IN_DIM;
#pragma unroll
        for (int k = 0; k < IN_DIM; k++) v[k] = xp[k] + ag[k] * inv;

#pragma unroll
        for (int j = 0; j < HID; j++) {
            float s = sb1[j];
#pragma unroll
            for (int k = 0; k < IN_DIM; k++) s = fmaf(v[k], sW1[k * HID + j], s);
            h1[j] = fmaxf(s, 0.0f);
        }
        // second layer: accumulate relu(h1@W2+b2) straight into the block sum
#pragma unroll 4
        for (int j = 0; j < HID; j++) {
            float s = sb2[j];
#pragma unroll
            for (int k = 0; k < HID; k++) s = fmaf(h1[k], sW2[k * HID + j], s);
            atomicAdd(&ssum[j], fmaxf(s, 0.0f));
        }
    }
    __syncthreads();
    if (tid < HID) atomicAdd(&g_hsum[tid], ssum[tid]);
}

// ---------------------------------------------------------------------------
// Finalize: out = tanh(mean @ Wh + bh)
// ---------------------------------------------------------------------------
__global__ void final_kernel(const float* __restrict__ Wh,
                             const float* __restrict__ bh,
                             float* __restrict__ out, int n) {
    __shared__ float red[HID];
    int tid = threadIdx.x;
    float v = (g_hsum[tid] / (float)n) * Wh[tid];
    red[tid] = v;
    __syncthreads();
    for (int s = HID / 2; s > 0; s >>= 1) {
        if (tid < s) red[tid] += red[tid + s];
        __syncthreads();
    }
    if (tid == 0) out[0] = tanhf(red[0] + bh[0]);
}

// ---------------------------------------------------------------------------
extern "C" void kernel_launch(void* const* d_in, const int* in_sizes, int n_in,
                              void* d_out, int out_size) {
    const float* x  = (const float*)d_in[0];
    const int*   ei = (const int*)d_in[1];
    const float* W1 = (const float*)d_in[2];
    const float* b1 = (const float*)d_in[3];
    const float* W2 = (const float*)d_in[4];
    const float* b2 = (const float*)d_in[5];
    const float* Wh = (const float*)d_in[6];
    const float* bh = (const float*)d_in[7];
    float* out = (float*)d_out;

    int n = in_sizes[0] / IN_DIM;
    int E = in_sizes[1] / 2;

    int zt = n * IN_DIM + n + HID;
    zero_kernel<<<(zt + 511) / 512, 512>>>(n);
    edge_kernel<<<(E + 255) / 256, 256>>>(ei, x, E, n);
    node_kernel<<<(n + 255) / 256, 256>>>(x, W1, b1, W2, b2, n);
    final_kernel<<<1, HID>>>(Wh, bh, out, n);
}